// round 5
// baseline (speedup 1.0000x reference)
#include <cuda_runtime.h>
#include <math.h>

// ---------------- problem constants ----------------
#define TT    4
#define BB    16
#define CINC  3
#define HIMG  64
#define WIMG  64
#define NN    6
#define COUT  128
#define HP    32
#define WP    32
#define NPIX  1024          // HP*WP
#define NODE5 5
#define KTOT  1152          // 128 ci * 9 taps
#define COG   640           // 5 nodes * 128 out channels

// ---------------- persistent device state ----------------
__device__ float g_v0[BB*COUT*HIMG*WIMG];        // 8,388,608
__device__ float g_vn[NODE5*BB*COUT*NPIX];       // 10,485,760
__device__ float g_traces[BB*NN*COUT];           // 12,288
__device__ float g_out0[BB*COUT*NPIX];           // 2,097,152
__device__ float g_m0[BB*COUT];                  // 2,048
__device__ float g_Y[BB*COG*NPIX];               // 10,485,760
__device__ float g_c[BB*NN];                     // 96
__device__ float g_nodesum[NODE5*BB*COUT];       // 10,240
__device__ float g_Wt[KTOT*COG];                 // 737,280

// ---------------- f32x2 helpers (Blackwell packed fp32) ----------------
__device__ __forceinline__ unsigned long long pack2(float lo, float hi) {
    unsigned long long r;
    asm("mov.b64 %0, {%1, %2};" : "=l"(r) : "f"(lo), "f"(hi));
    return r;
}
__device__ __forceinline__ unsigned long long fma2(unsigned long long a,
                                                   unsigned long long b,
                                                   unsigned long long c) {
    unsigned long long d;
    asm("fma.rn.f32x2 %0, %1, %2, %3;" : "=l"(d) : "l"(a), "l"(b), "l"(c));
    return d;
}
__device__ __forceinline__ float2 unpack2(unsigned long long v) {
    float2 r;
    asm("mov.b64 {%0, %1}, %2;" : "=f"(r.x), "=f"(r.y) : "l"(v));
    return r;
}

__device__ __forceinline__ float sigmoidf(float x) { return 1.0f / (1.0f + expf(-x)); }

// ---------------- K0: zero persistent state ----------------
__global__ void kzero() {
    long long tid = (long long)blockIdx.x * blockDim.x + threadIdx.x;
    long long stride = (long long)gridDim.x * blockDim.x;
    for (long long i = tid; i < (long long)BB*COUT*HIMG*WIMG; i += stride) g_v0[i] = 0.0f;
    for (long long i = tid; i < (long long)NODE5*BB*COUT*NPIX; i += stride) g_vn[i] = 0.0f;
    for (long long i = tid; i < (long long)BB*NN*COUT; i += stride) g_traces[i] = 0.0f;
}

// ---------------- Kw: transpose node-conv weights to [k=(tap,ci)][cog] ----------------
__global__ void kw_transpose(const float* __restrict__ w) {
    int idx = blockIdx.x * 256 + threadIdx.x;
    if (idx >= KTOT * COG) return;
    int k   = idx / COG;
    int cog = idx - k * COG;
    int tap = k >> 7;         // 0..8
    int ci  = k & 127;
    // convs_w flat: cog*1152 + ci*9 + tap
    g_Wt[idx] = w[cog * KTOT + ci * 9 + tap];
}

// ---------------- K1: conv0(3->128) + BN + PLIF0 + 2x2 avgpool -> out0 ----------------
__global__ void k1_conv0(const float* __restrict__ xt, const float* __restrict__ w0,
                         const float* __restrict__ bg, const float* __restrict__ bb,
                         const float* __restrict__ bm, const float* __restrict__ bv,
                         const float* __restrict__ plifw) {
    int tid = blockIdx.x * 256 + threadIdx.x;      // B*COUT*NPIX = 2,097,152 threads
    int p   = tid & (NPIX - 1);
    int co  = (tid >> 10) & 127;
    int b   = tid >> 17;
    int hp  = p >> 5, wp = p & 31;

    float w[27];
#pragma unroll
    for (int j = 0; j < 27; j++) w[j] = __ldg(w0 + co * 27 + j);
    float inv   = 1.0f / sqrtf(__ldg(bv + co) + 1e-5f);
    float ga    = __ldg(bg + co) * inv;
    float mm    = __ldg(bm + co);
    float bbias = __ldg(bb + co);
    float sig   = sigmoidf(__ldg(plifw));

    const float* xb = xt + b * (CINC * HIMG * WIMG);
    float s4 = 0.0f;
#pragma unroll
    for (int dy = 0; dy < 2; dy++)
#pragma unroll
        for (int dx = 0; dx < 2; dx++) {
            int y0 = 2 * hp + dy, x0 = 2 * wp + dx;
            float acc = 0.0f;
#pragma unroll
            for (int ci = 0; ci < 3; ci++)
#pragma unroll
                for (int ky = 0; ky < 3; ky++) {
                    int yy = y0 + ky - 1;
                    if (yy < 0 || yy >= HIMG) continue;
#pragma unroll
                    for (int kx = 0; kx < 3; kx++) {
                        int xx = x0 + kx - 1;
                        if (xx < 0 || xx >= WIMG) continue;
                        acc += xb[ci * (HIMG*WIMG) + yy * WIMG + xx] * w[ci * 9 + ky * 3 + kx];
                    }
                }
            float xc = (acc - mm) * ga + bbias;
            int vi = ((b * COUT + co) * HIMG + y0) * WIMG + x0;
            float vprev = g_v0[vi];
            float v = vprev + (xc - vprev) * sig;
            float sp = (v >= 1.0f) ? 1.0f : 0.0f;
            g_v0[vi] = v * (1.0f - sp);
            s4 += sp;
        }
    g_out0[(b * COUT + co) * NPIX + p] = s4 * 0.25f;
}

// ---------------- K2a: spatial mean of out0 -> g_m0 ----------------
__global__ void k2a_mean() {
    __shared__ float red[256];
    int bc = blockIdx.x;                           // 0..2047 = b*128+co
    const float* src = g_out0 + bc * NPIX;
    int t = threadIdx.x;
    float s = src[t] + src[t + 256] + src[t + 512] + src[t + 768];
    red[t] = s; __syncthreads();
    for (int st = 128; st > 0; st >>= 1) {
        if (t < st) red[t] += red[t + st];
        __syncthreads();
    }
    if (t == 0) g_m0[bc] = red[0] * (1.0f / 1024.0f);
}

// ---------------- K2b: feat0 + mid-update of traces[:,0,:] ----------------
__global__ void k2b_feat0(const float* __restrict__ ftw, const float* __restrict__ ftb) {
    int b = blockIdx.x, co = threadIdx.x;
    __shared__ float mv[128];
    mv[co] = g_m0[b * 128 + co];
    __syncthreads();
    float acc = 0.0f;
    for (int ci = 0; ci < 128; ci++) acc += mv[ci] * __ldg(ftw + co * 128 + ci);
    float f = fmaxf(acc + __ldg(ftb + co), 0.0f);
    int ti = (b * NN + 0) * 128 + co;
    g_traces[ti] = 0.6f * g_traces[ti] + 0.4f * f;
}

// ---------------- K3: GAT adjacency + softmax + top-k prune + diffusion -> c ----------------
__global__ void k3_gat(const float* __restrict__ gw, const float* __restrict__ ga) {
    int b = blockIdx.x;
    __shared__ float tr[768], hps[768], e1s[24], e2s[24];
    int tid = threadIdx.x;                         // 192 threads
    for (int o = tid; o < 768; o += 192) tr[o] = g_traces[b * 768 + o];
    __syncthreads();
    for (int o = tid; o < 768; o += 192) {
        int n = o >> 7, co = o & 127;
        float s = 0.0f;
        for (int ci = 0; ci < 128; ci++) s += tr[n * 128 + ci] * __ldg(gw + co * 128 + ci);
        hps[o] = s;
    }
    __syncthreads();
    if (tid < 24) {
        int n = tid >> 2, h = tid & 3;
        float s1 = 0.0f, s2 = 0.0f;
        for (int d = 0; d < 32; d++) {
            float hv = hps[n * 128 + h * 32 + d];
            s1 += hv * __ldg(ga + h * 64 + d);
            s2 += hv * __ldg(ga + h * 64 + 32 + d);
        }
        e1s[tid] = s1; e2s[tid] = s2;
    }
    __syncthreads();
    if (tid == 0) {
        float S[6][6], Sp[6][6], adj[6][6], op[6][6], deg[6], dis[6];
        for (int i = 0; i < 6; i++)
            for (int j = 0; j < 6; j++) {
                float s = 0.0f;
                for (int h = 0; h < 4; h++) {
                    float eij = e1s[i*4+h] + e2s[j*4+h];
                    eij = eij > 0.0f ? eij : 0.2f * eij;
                    float eji = e1s[j*4+h] + e2s[i*4+h];
                    eji = eji > 0.0f ? eji : 0.2f * eji;
                    s += 0.5f * (eij + eji);
                }
                S[i][j] = s * 0.25f;                 // mean over heads
            }
        // softmax(attn / 0.01) row-wise
        for (int i = 0; i < 6; i++) {
            float y[6], mx = -1e30f;
            for (int j = 0; j < 6; j++) { y[j] = S[i][j] / 0.01f; mx = fmaxf(mx, y[j]); }
            float den = 0.0f;
            for (int j = 0; j < 6; j++) { y[j] = expf(y[j] - mx); den += y[j]; }
            for (int j = 0; j < 6; j++) S[i][j] = y[j] / den;
        }
        // prune: keep entries >= 3rd largest per row
        for (int i = 0; i < 6; i++) {
            float v[6];
            for (int j = 0; j < 6; j++) v[j] = S[i][j];
            for (int a = 0; a < 3; a++) {
                int mi = a;
                for (int q = a + 1; q < 6; q++) if (v[q] > v[mi]) mi = q;
                float tmp = v[a]; v[a] = v[mi]; v[mi] = tmp;
            }
            float kth = v[2];
            for (int j = 0; j < 6; j++)
                Sp[i][j] = S[i][j] * ((S[i][j] >= kth) ? 1.0f : 0.0f);
        }
        // diffusion op
        for (int i = 0; i < 6; i++) {
            float dsum = 0.0f;
            for (int j = 0; j < 6; j++) { adj[i][j] = 0.5f * (Sp[i][j] + Sp[j][i]); dsum += adj[i][j]; }
            deg[i] = dsum;
        }
        for (int i = 0; i < 6; i++) dis[i] = 1.0f / sqrtf(deg[i] + 1e-6f);
        for (int i = 0; i < 6; i++)
            for (int j = 0; j < 6; j++) op[i][j] = dis[i] * adj[i][j] * dis[j];
        // c = (op @ op)[:, 0]
        for (int i = 0; i < 6; i++) {
            float cv = 0.0f;
            for (int j = 0; j < 6; j++) cv += op[i][j] * op[j][0];
            g_c[b * NN + i] = cv;
        }
    }
}

// ---------------- K4: fused 5-node conv = implicit GEMM 640x1024 @ K=1152 (f32x2) ------
__global__ __launch_bounds__(256, 2) void k4_conv() {
    const int b   = blockIdx.z;
    const int co0 = blockIdx.x * 128;               // 5 tiles of 128 over 640
    const int p0  = blockIdx.y * 128;               // 8 tiles of 128 over 1024
    const int tid = threadIdx.x;

    __shared__ float As[8][128];
    __shared__ float Bs[8][128];

    unsigned long long acc[8][4];
#pragma unroll
    for (int i = 0; i < 8; i++)
#pragma unroll
        for (int j = 0; j < 4; j++) acc[i][j] = 0ull;

    const int it = tid >> 4;        // 0..15 : co sub-block (8 channels)
    const int jt = tid & 15;        // 0..15 : pixel sub-block (8 pixels)
    const int lk  = tid >> 5;       // 0..7  : k row loaded by this thread
    const int lc4 = (tid & 31) << 2;// 0,4,..,124 : column*4
    const int lrow = (p0 >> 5) + (lc4 >> 5);   // out0 row for B-tile element
    const int lwp  = lc4 & 31;

    const float* out0b = g_out0 + b * (COUT * NPIX);

#pragma unroll 1
    for (int tap = 0; tap < 9; tap++) {
        const int ky = tap / 3 - 1;
        const int kx = tap % 3 - 1;
        const int y  = lrow + ky;
        const bool yok = (y >= 0) && (y < 32);
#pragma unroll 1
        for (int cc = 0; cc < 16; cc++) {
            const int ci = cc * 8 + lk;
            // A tile: coalesced from pre-transposed weights
            float4 av = *(const float4*)(g_Wt + (tap * 128 + ci) * COG + co0 + lc4);
            // B tile: on-the-fly im2col of out0 with zero padding
            float bv0 = 0.f, bv1 = 0.f, bv2 = 0.f, bv3 = 0.f;
            if (yok) {
                const float* src = out0b + ci * NPIX + y * 32;
                int x0 = lwp + kx;
                bv0 = (x0     >= 0 && x0     < 32) ? src[x0]     : 0.f;
                bv1 = (x0 + 1 >= 0 && x0 + 1 < 32) ? src[x0 + 1] : 0.f;
                bv2 = (x0 + 2 >= 0 && x0 + 2 < 32) ? src[x0 + 2] : 0.f;
                bv3 = (x0 + 3 >= 0 && x0 + 3 < 32) ? src[x0 + 3] : 0.f;
            }
            *(float4*)&As[lk][lc4] = av;
            float4 bvv; bvv.x = bv0; bvv.y = bv1; bvv.z = bv2; bvv.w = bv3;
            *(float4*)&Bs[lk][lc4] = bvv;
            __syncthreads();
#pragma unroll
            for (int kk = 0; kk < 8; kk++) {
                float4 a0 = *(const float4*)&As[kk][it * 8];
                float4 a1 = *(const float4*)&As[kk][it * 8 + 4];
                float4 b0 = *(const float4*)&Bs[kk][jt * 8];
                float4 b1 = *(const float4*)&Bs[kk][jt * 8 + 4];
                unsigned long long bp0 = pack2(b0.x, b0.y);
                unsigned long long bp1 = pack2(b0.z, b0.w);
                unsigned long long bp2 = pack2(b1.x, b1.y);
                unsigned long long bp3 = pack2(b1.z, b1.w);
                float aa[8] = {a0.x, a0.y, a0.z, a0.w, a1.x, a1.y, a1.z, a1.w};
#pragma unroll
                for (int i = 0; i < 8; i++) {
                    unsigned long long ap = pack2(aa[i], aa[i]);
                    acc[i][0] = fma2(ap, bp0, acc[i][0]);
                    acc[i][1] = fma2(ap, bp1, acc[i][1]);
                    acc[i][2] = fma2(ap, bp2, acc[i][2]);
                    acc[i][3] = fma2(ap, bp3, acc[i][3]);
                }
            }
            __syncthreads();
        }
    }
    // epilogue: Y[b][cog][p]
    float* yb = g_Y + ((long long)b * COG + co0 + it * 8) * NPIX + p0 + jt * 8;
#pragma unroll
    for (int i = 0; i < 8; i++)
#pragma unroll
        for (int j = 0; j < 4; j++) {
            float2 r = unpack2(acc[i][j]);
            *(float2*)(yb + i * NPIX + j * 2) = r;
        }
}

// ---------------- K5: node BN + PLIF + weighted output + spike sums ----------------
__global__ void k5_nodes(const float* __restrict__ bg, const float* __restrict__ bb,
                         const float* __restrict__ bm, const float* __restrict__ bv,
                         const float* __restrict__ plifw, const float* __restrict__ outw,
                         float* __restrict__ out, int t) {
    int blk = blockIdx.x;
    int b = blk >> 7, co = blk & 127;
    int tid = threadIdx.x;

    float wsig[6];
#pragma unroll
    for (int i = 0; i < 6; i++) wsig[i] = sigmoidf(__ldg(outw + i));

    float sigp[5], ga[5], mm[5], bbias[5], cv[5];
#pragma unroll
    for (int i = 0; i < 5; i++) {
        sigp[i] = sigmoidf(__ldg(plifw + 1 + i));
        float inv = 1.0f / sqrtf(__ldg(bv + i * 128 + co) + 1e-5f);
        ga[i]    = __ldg(bg + i * 128 + co) * inv;
        mm[i]    = __ldg(bm + i * 128 + co);
        bbias[i] = __ldg(bb + i * 128 + co);
        cv[i]    = g_c[b * NN + 1 + i];
    }

    float lsum[5] = {0, 0, 0, 0, 0};
    const int base0 = (b * COUT + co) * NPIX;
#pragma unroll
    for (int q = 0; q < 4; q++) {
        int pp = tid + q * 256;
        float o0 = g_out0[base0 + pp];
        float accO = wsig[0] * o0;
#pragma unroll
        for (int i = 0; i < 5; i++) {
            float yv = g_Y[((long long)b * COG + i * 128 + co) * NPIX + pp];
            float pre = cv[i] * yv;
            float civ = (pre - mm[i]) * ga[i] + bbias[i];
            int vidx = ((i * BB + b) * COUT + co) * NPIX + pp;
            float vp = g_vn[vidx];
            float v = vp + (civ - vp) * sigp[i];
            float sp = (v >= 1.0f) ? 1.0f : 0.0f;
            g_vn[vidx] = v * (1.0f - sp);
            accO += wsig[i + 1] * sp;
            lsum[i] += sp;
        }
        out[((long long)(t * BB + b) * COUT + co) * NPIX + pp] = accO;
    }

    __shared__ float red[256];
    for (int i = 0; i < 5; i++) {
        red[tid] = lsum[i];
        __syncthreads();
        for (int st = 128; st > 0; st >>= 1) {
            if (tid < st) red[tid] += red[tid + st];
            __syncthreads();
        }
        if (tid == 0) g_nodesum[i * (BB * COUT) + b * COUT + co] = red[0];
        __syncthreads();
    }
}

// ---------------- K6: all-node feats + final traces update ----------------
__global__ void k6_feats(const float* __restrict__ ftw, const float* __restrict__ ftb) {
    int b = blockIdx.x / NN, n = blockIdx.x % NN;
    int co = threadIdx.x;
    __shared__ float mv[128];
    mv[co] = (n == 0) ? g_m0[b * 128 + co]
                      : g_nodesum[(n - 1) * (BB * COUT) + b * 128 + co] * (1.0f / 1024.0f);
    __syncthreads();
    float acc = 0.0f;
    for (int ci = 0; ci < 128; ci++) acc += mv[ci] * __ldg(ftw + co * 128 + ci);
    float f = fmaxf(acc + __ldg(ftb + co), 0.0f);
    int ti = (b * NN + n) * 128 + co;
    g_traces[ti] = 0.6f * g_traces[ti] + 0.4f * f;
}

// ---------------- launcher ----------------
extern "C" void kernel_launch(void* const* d_in, const int* in_sizes, int n_in,
                              void* d_out, int out_size) {
    const float* x       = (const float*)d_in[0];
    const float* conv0_w = (const float*)d_in[1];
    const float* bn0_g   = (const float*)d_in[2];
    const float* bn0_b   = (const float*)d_in[3];
    const float* bn0_m   = (const float*)d_in[4];
    const float* bn0_v   = (const float*)d_in[5];
    const float* convs_w = (const float*)d_in[6];
    const float* bns_g   = (const float*)d_in[7];
    const float* bns_b   = (const float*)d_in[8];
    const float* bns_m   = (const float*)d_in[9];
    const float* bns_v   = (const float*)d_in[10];
    const float* plif_w  = (const float*)d_in[11];
    const float* ft_w    = (const float*)d_in[12];
    const float* ft_b    = (const float*)d_in[13];
    const float* gat_W   = (const float*)d_in[14];
    const float* gat_a   = (const float*)d_in[15];
    const float* out_w   = (const float*)d_in[16];
    float* out = (float*)d_out;

    kzero<<<4096, 256>>>();
    kw_transpose<<<(KTOT * COG + 255) / 256, 256>>>(convs_w);

    for (int t = 0; t < TT; t++) {
        k1_conv0<<<(BB * COUT * NPIX) / 256, 256>>>(
            x + (long long)t * BB * CINC * HIMG * WIMG,
            conv0_w, bn0_g, bn0_b, bn0_m, bn0_v, plif_w);
        k2a_mean<<<BB * COUT, 256>>>();
        k2b_feat0<<<BB, 128>>>(ft_w, ft_b);
        k3_gat<<<BB, 192>>>(gat_W, gat_a);
        k4_conv<<<dim3(5, 8, BB), 256>>>();
        k5_nodes<<<BB * COUT, 256>>>(bns_g, bns_b, bns_m, bns_v, plif_w, out_w, out, t);
        k6_feats<<<BB * NN, 128>>>(ft_w, ft_b);
    }
}

// round 9
// speedup vs baseline: 1.7322x; 1.7322x over previous
#include <cuda_runtime.h>
#include <cuda_bf16.h>
#include <math.h>
#include <stdint.h>

// ---------------- problem constants ----------------
#define TT    4
#define BB    16
#define CINC  3
#define HIMG  64
#define WIMG  64
#define NN    6
#define COUT  128
#define HP    32
#define WP    32
#define NPIX  1024
#define NODE5 5
#define KTOT  1152          // 128 ci * 9 taps
#define COG   640           // 5 nodes * 128 out channels
#define NCHUNK 18           // 1152 / 64

// ---------------- persistent device state ----------------
__device__ float g_v0[BB*COUT*HIMG*WIMG];
__device__ float g_vn[NODE5*BB*COUT*NPIX];
__device__ float g_traces[BB*NN*COUT];
__device__ float g_out0[BB*COUT*NPIX];
__device__ float g_m0[BB*COUT];
__device__ float g_Y[BB*COG*NPIX];
__device__ float g_c[BB*NN];
__device__ float g_nodesum[NODE5*BB*COUT];
__device__ __nv_bfloat16 g_A[3*COG*KTOT];        // 3-split weights, k = tap*128+ci
__device__ __nv_bfloat16 g_B[BB*NPIX*KTOT];      // im2col of out0, bf16 (exact)

__device__ __forceinline__ float sigmoidf(float x) { return 1.0f / (1.0f + expf(-x)); }

// ================= baseline-ISA helpers (sm_80+: valid on sm_103 target) =======
__device__ __forceinline__ uint32_t smem_u32(const void* p) {
    uint32_t a;
    asm("{ .reg .u64 t; cvta.to.shared.u64 t, %1; cvt.u32.u64 %0, t; }" : "=r"(a) : "l"(p));
    return a;
}
#define SWZ128(off) ((off) ^ (((off) >> 3) & 0x70))
#define CP16(dst, src) \
    asm volatile("cp.async.cg.shared.global [%0], [%1], 16;" :: "r"(dst), "l"(src) : "memory")
#define CP_COMMIT() asm volatile("cp.async.commit_group;" ::: "memory")
#define CP_WAIT(n)  asm volatile("cp.async.wait_group %0;" :: "n"(n) : "memory")

__device__ __forceinline__ void ldsm4(uint32_t& r0, uint32_t& r1, uint32_t& r2,
                                      uint32_t& r3, uint32_t addr) {
    asm volatile("ldmatrix.sync.aligned.m8n8.x4.shared.b16 {%0,%1,%2,%3}, [%4];"
                 : "=r"(r0), "=r"(r1), "=r"(r2), "=r"(r3) : "r"(addr));
}
__device__ __forceinline__ void mma_bf16(float* c, uint32_t a0, uint32_t a1,
                                         uint32_t a2, uint32_t a3,
                                         uint32_t b0, uint32_t b1) {
    asm volatile("mma.sync.aligned.m16n8k16.row.col.f32.bf16.bf16.f32 "
                 "{%0,%1,%2,%3}, {%4,%5,%6,%7}, {%8,%9}, {%0,%1,%2,%3};"
                 : "+f"(c[0]), "+f"(c[1]), "+f"(c[2]), "+f"(c[3])
                 : "r"(a0), "r"(a1), "r"(a2), "r"(a3), "r"(b0), "r"(b1));
}

// ---------------- K0: zero persistent state ----------------
__global__ void kzero() {
    long long tid = (long long)blockIdx.x * blockDim.x + threadIdx.x;
    long long stride = (long long)gridDim.x * blockDim.x;
    for (long long i = tid; i < (long long)BB*COUT*HIMG*WIMG; i += stride) g_v0[i] = 0.0f;
    for (long long i = tid; i < (long long)NODE5*BB*COUT*NPIX; i += stride) g_vn[i] = 0.0f;
    for (long long i = tid; i < (long long)BB*NN*COUT; i += stride) g_traces[i] = 0.0f;
}

// ---------------- Ka: build 3-way bf16 split of node-conv weights (once) --------
__global__ void ka_build(const float* __restrict__ w) {
    int idx = blockIdx.x * 256 + threadIdx.x;
    if (idx >= COG * KTOT) return;
    int cog = idx / KTOT;
    int k   = idx - cog * KTOT;
    int tap = k >> 7;
    int ci  = k & 127;
    float v = w[cog * KTOT + ci * 9 + tap];
    __nv_bfloat16 h0 = __float2bfloat16(v);
    float f0 = __bfloat162float(h0);
    __nv_bfloat16 h1 = __float2bfloat16(v - f0);
    float f1 = __bfloat162float(h1);
    __nv_bfloat16 h2 = __float2bfloat16(v - f0 - f1);
    g_A[idx]                = h0;
    g_A[COG*KTOT + idx]     = h1;
    g_A[2*COG*KTOT + idx]   = h2;
}

// ---------------- K1: conv0(3->128)+BN+PLIF0+2x2 avgpool -> out0 ----------------
__global__ void k1_conv0(const float* __restrict__ xt, const float* __restrict__ w0,
                         const float* __restrict__ bg, const float* __restrict__ bb,
                         const float* __restrict__ bm, const float* __restrict__ bv,
                         const float* __restrict__ plifw) {
    int tid = blockIdx.x * 256 + threadIdx.x;
    int p   = tid & (NPIX - 1);
    int co  = (tid >> 10) & 127;
    int b   = tid >> 17;
    int hp  = p >> 5, wp = p & 31;

    float w[27];
#pragma unroll
    for (int j = 0; j < 27; j++) w[j] = __ldg(w0 + co * 27 + j);
    float inv   = 1.0f / sqrtf(__ldg(bv + co) + 1e-5f);
    float ga    = __ldg(bg + co) * inv;
    float mm    = __ldg(bm + co);
    float bbias = __ldg(bb + co);
    float sig   = sigmoidf(__ldg(plifw));

    const float* xb = xt + b * (CINC * HIMG * WIMG);
    float s4 = 0.0f;
#pragma unroll
    for (int dy = 0; dy < 2; dy++)
#pragma unroll
        for (int dx = 0; dx < 2; dx++) {
            int y0 = 2 * hp + dy, x0 = 2 * wp + dx;
            float acc = 0.0f;
#pragma unroll
            for (int ci = 0; ci < 3; ci++)
#pragma unroll
                for (int ky = 0; ky < 3; ky++) {
                    int yy = y0 + ky - 1;
                    if (yy < 0 || yy >= HIMG) continue;
#pragma unroll
                    for (int kx = 0; kx < 3; kx++) {
                        int xx = x0 + kx - 1;
                        if (xx < 0 || xx >= WIMG) continue;
                        acc += xb[ci * (HIMG*WIMG) + yy * WIMG + xx] * w[ci * 9 + ky * 3 + kx];
                    }
                }
            float xc = (acc - mm) * ga + bbias;
            int vi = ((b * COUT + co) * HIMG + y0) * WIMG + x0;
            float vprev = g_v0[vi];
            float v = vprev + (xc - vprev) * sig;
            float sp = (v >= 1.0f) ? 1.0f : 0.0f;
            g_v0[vi] = v * (1.0f - sp);
            s4 += sp;
        }
    g_out0[(b * COUT + co) * NPIX + p] = s4 * 0.25f;
}

// ---------------- Kb: im2col of out0 -> g_B (bf16, exact) per timestep ----------
__global__ void kb_im2col() {
    int y = blockIdx.x, b = blockIdx.y;
    __shared__ __nv_bfloat16 st[3][34][130];
    int tid = threadIdx.x;
    for (int i = tid; i < 3 * 130; i += 256) {
        int r = i / 130, ci = i - r * 130;
        st[r][0][ci]  = __float2bfloat16(0.0f);
        st[r][33][ci] = __float2bfloat16(0.0f);
    }
    __syncthreads();
#pragma unroll 4
    for (int it = 0; it < 48; it++) {
        int f = it * 256 + tid;
        int ci = f / 96;
        int r3 = (f % 96) >> 5;
        int x  = f & 31;
        int yy = y + r3 - 1;
        float v = (yy >= 0 && yy < 32) ? g_out0[(b * 128 + ci) * NPIX + yy * 32 + x] : 0.0f;
        st[r3][x + 1][ci] = __float2bfloat16(v);
    }
    __syncthreads();
    __nv_bfloat16* dst = g_B + (long long)(b * NPIX + y * 32) * KTOT;
#pragma unroll 4
    for (int it = 0; it < 72; it++) {
        int f = it * 256 + tid;
        int cp  = f & 63;
        int tap = (f >> 6) % 9;
        int x   = f / 576;
        int ky = tap / 3, kx = tap % 3;
        __nv_bfloat162 vv;
        vv.x = st[ky][x + kx][2 * cp];
        vv.y = st[ky][x + kx][2 * cp + 1];
        *reinterpret_cast<__nv_bfloat162*>(dst + (long long)x * KTOT + tap * 128 + 2 * cp) = vv;
    }
}

// ---------------- K2a/K2b/K3 (small control-path kernels) ----------------
__global__ void k2a_mean() {
    __shared__ float red[256];
    int bc = blockIdx.x;
    const float* src = g_out0 + bc * NPIX;
    int t = threadIdx.x;
    float s = src[t] + src[t + 256] + src[t + 512] + src[t + 768];
    red[t] = s; __syncthreads();
    for (int st = 128; st > 0; st >>= 1) {
        if (t < st) red[t] += red[t + st];
        __syncthreads();
    }
    if (t == 0) g_m0[bc] = red[0] * (1.0f / 1024.0f);
}

__global__ void k2b_feat0(const float* __restrict__ ftw, const float* __restrict__ ftb) {
    int b = blockIdx.x, co = threadIdx.x;
    __shared__ float mv[128];
    mv[co] = g_m0[b * 128 + co];
    __syncthreads();
    float acc = 0.0f;
    for (int ci = 0; ci < 128; ci++) acc += mv[ci] * __ldg(ftw + co * 128 + ci);
    float f = fmaxf(acc + __ldg(ftb + co), 0.0f);
    int ti = (b * NN + 0) * 128 + co;
    g_traces[ti] = 0.6f * g_traces[ti] + 0.4f * f;
}

__global__ void k3_gat(const float* __restrict__ gw, const float* __restrict__ ga) {
    int b = blockIdx.x;
    __shared__ float tr[768], hps[768], e1s[24], e2s[24];
    int tid = threadIdx.x;
    for (int o = tid; o < 768; o += 192) tr[o] = g_traces[b * 768 + o];
    __syncthreads();
    for (int o = tid; o < 768; o += 192) {
        int n = o >> 7, co = o & 127;
        float s = 0.0f;
        for (int ci = 0; ci < 128; ci++) s += tr[n * 128 + ci] * __ldg(gw + co * 128 + ci);
        hps[o] = s;
    }
    __syncthreads();
    if (tid < 24) {
        int n = tid >> 2, h = tid & 3;
        float s1 = 0.0f, s2 = 0.0f;
        for (int d = 0; d < 32; d++) {
            float hv = hps[n * 128 + h * 32 + d];
            s1 += hv * __ldg(ga + h * 64 + d);
            s2 += hv * __ldg(ga + h * 64 + 32 + d);
        }
        e1s[tid] = s1; e2s[tid] = s2;
    }
    __syncthreads();
    if (tid == 0) {
        float S[6][6], Sp[6][6], adj[6][6], op[6][6], deg[6], dis[6];
        for (int i = 0; i < 6; i++)
            for (int j = 0; j < 6; j++) {
                float s = 0.0f;
                for (int h = 0; h < 4; h++) {
                    float eij = e1s[i*4+h] + e2s[j*4+h];
                    eij = eij > 0.0f ? eij : 0.2f * eij;
                    float eji = e1s[j*4+h] + e2s[i*4+h];
                    eji = eji > 0.0f ? eji : 0.2f * eji;
                    s += 0.5f * (eij + eji);
                }
                S[i][j] = s * 0.25f;
            }
        for (int i = 0; i < 6; i++) {
            float y[6], mx = -1e30f;
            for (int j = 0; j < 6; j++) { y[j] = S[i][j] / 0.01f; mx = fmaxf(mx, y[j]); }
            float den = 0.0f;
            for (int j = 0; j < 6; j++) { y[j] = expf(y[j] - mx); den += y[j]; }
            for (int j = 0; j < 6; j++) S[i][j] = y[j] / den;
        }
        for (int i = 0; i < 6; i++) {
            float v[6];
            for (int j = 0; j < 6; j++) v[j] = S[i][j];
            for (int a = 0; a < 3; a++) {
                int mi = a;
                for (int q = a + 1; q < 6; q++) if (v[q] > v[mi]) mi = q;
                float tmp = v[a]; v[a] = v[mi]; v[mi] = tmp;
            }
            float kth = v[2];
            for (int j = 0; j < 6; j++)
                Sp[i][j] = S[i][j] * ((S[i][j] >= kth) ? 1.0f : 0.0f);
        }
        for (int i = 0; i < 6; i++) {
            float dsum = 0.0f;
            for (int j = 0; j < 6; j++) { adj[i][j] = 0.5f * (Sp[i][j] + Sp[j][i]); dsum += adj[i][j]; }
            deg[i] = dsum;
        }
        for (int i = 0; i < 6; i++) dis[i] = 1.0f / sqrtf(deg[i] + 1e-6f);
        for (int i = 0; i < 6; i++)
            for (int j = 0; j < 6; j++) op[i][j] = dis[i] * adj[i][j] * dis[j];
        for (int i = 0; i < 6; i++) {
            float cv = 0.0f;
            for (int j = 0; j < 6; j++) cv += op[i][j] * op[j][0];
            g_c[b * NN + i] = cv;
        }
    }
}

// ---------------- K4: mma.sync bf16 GEMM (128co x 256pix tile) -----------------
// grid (5 co-tiles, 4 pix-tiles, 16 b), 256 threads (8 warps: 2m x 4n).
// D[128 x 256] = sum_{split,k} A3[split][co][k] * B[pix][k]
#define ASTAGE 49152                 // 3 * 128 rows * 128B
#define BSTAGE 32768                 // 256 rows * 128B
#define STAGE  (ASTAGE + BSTAGE)     // 81920
#define K4_SMEM (2 * STAGE)          // 163840

__device__ __forceinline__ void load_chunk(uint32_t sb, int stage, int c,
                                           const __nv_bfloat16* gA,
                                           const __nv_bfloat16* gB, int tid) {
    uint32_t abase = sb + stage * STAGE;
    uint32_t bbase = abase + ASTAGE;
#pragma unroll
    for (int i = 0; i < 12; i++) {               // A: 3 splits * 128 rows * 8 x 16B
        int idx = i * 256 + tid;
        int split = idx >> 10;
        int rem = idx & 1023;
        int r = rem >> 3, j = rem & 7;
        const __nv_bfloat16* src = gA + ((long long)(split * COG + r)) * KTOT + c * 64 + j * 8;
        uint32_t off = (uint32_t)(r * 128 + j * 16);
        CP16(abase + split * 16384 + SWZ128(off), src);
    }
#pragma unroll
    for (int i = 0; i < 8; i++) {                // B: 256 rows * 8 x 16B
        int idx = i * 256 + tid;
        int n = idx >> 3, j = idx & 7;
        const __nv_bfloat16* src = gB + (long long)n * KTOT + c * 64 + j * 8;
        uint32_t off = (uint32_t)(n * 128 + j * 16);
        CP16(bbase + SWZ128(off), src);
    }
}

__global__ __launch_bounds__(256, 1) void k4_mma() {
    extern __shared__ char smem[];
    uint32_t sb = smem_u32(smem);
    const int tid = threadIdx.x;
    const int wid = tid >> 5;
    const int lid = tid & 31;
    const int co0 = blockIdx.x * 128;
    const int p0  = blockIdx.y * 256;
    const int b   = blockIdx.z;
    const int wm  = (wid >> 2) * 64;   // warp m offset (0 / 64)
    const int wn  = (wid & 3) * 64;    // warp n offset (0..192)

    const __nv_bfloat16* gA = g_A + (long long)co0 * KTOT;    // split offset inside loader
    const __nv_bfloat16* gB = g_B + (long long)(b * NPIX + p0) * KTOT;

    float acc[4][8][4];
#pragma unroll
    for (int i = 0; i < 4; i++)
#pragma unroll
        for (int j = 0; j < 8; j++)
#pragma unroll
            for (int q = 0; q < 4; q++) acc[i][j][q] = 0.0f;

    // per-lane ldmatrix base offsets (within a 16x16 / 16(rows) region)
    const int lrow = lid & 15;         // row within 16
    const int lcol = (lid >> 4) * 16;  // byte col half (0 / 16)

    load_chunk(sb, 0, 0, gA, gB, tid);
    CP_COMMIT();

#pragma unroll 1
    for (int c = 0; c < NCHUNK; c++) {
        const int s = c & 1;
        if (c + 1 < NCHUNK) {
            load_chunk(sb, s ^ 1, c + 1, gA, gB, tid);
            CP_COMMIT();
            CP_WAIT(1);
        } else {
            CP_WAIT(0);
        }
        __syncthreads();

        const uint32_t abase = sb + s * STAGE;
        const uint32_t bbase = abase + ASTAGE;
#pragma unroll
        for (int ks = 0; ks < 4; ks++) {
            const int kb = ks * 32;    // byte offset of k-step within 128B row
            // B fragments: 4 x ldmatrix.x4 covering 8 n-tiles of 8
            uint32_t bf[4][4];
#pragma unroll
            for (int q = 0; q < 4; q++) {
                uint32_t addr = bbase + SWZ128((uint32_t)((wn + q * 16 + lrow) * 128 + kb + lcol));
                ldsm4(bf[q][0], bf[q][1], bf[q][2], bf[q][3], addr);
            }
#pragma unroll
            for (int split = 0; split < 3; split++) {
                const uint32_t asb = abase + split * 16384;
#pragma unroll
                for (int mt = 0; mt < 4; mt++) {
                    uint32_t a0, a1, a2, a3;
                    uint32_t addr = asb + SWZ128((uint32_t)((wm + mt * 16 + lrow) * 128 + kb + lcol));
                    ldsm4(a0, a1, a2, a3, addr);
#pragma unroll
                    for (int q = 0; q < 4; q++) {
                        mma_bf16(acc[mt][2*q],   a0, a1, a2, a3, bf[q][0], bf[q][2]);
                        mma_bf16(acc[mt][2*q+1], a0, a1, a2, a3, bf[q][1], bf[q][3]);
                    }
                }
            }
        }
        __syncthreads();
    }

    // epilogue: accum regs -> g_Y (co-major rows, pix cols; float2 stores)
    const int er = lid >> 2;           // row within 8-group
    const int ec = (lid & 3) * 2;      // col pair
    float* ybase = g_Y + (long long)(b * COG + co0 + wm) * NPIX + p0 + wn;
#pragma unroll
    for (int mt = 0; mt < 4; mt++) {
#pragma unroll
        for (int nt = 0; nt < 8; nt++) {
            float* y0 = ybase + (long long)(mt * 16 + er) * NPIX + nt * 8 + ec;
            *reinterpret_cast<float2*>(y0) = make_float2(acc[mt][nt][0], acc[mt][nt][1]);
            float* y1 = y0 + 8 * NPIX;
            *reinterpret_cast<float2*>(y1) = make_float2(acc[mt][nt][2], acc[mt][nt][3]);
        }
    }
}

// ---------------- K5: node BN + PLIF + weighted output + spike sums ----------
__global__ void k5_nodes(const float* __restrict__ bg, const float* __restrict__ bb,
                         const float* __restrict__ bm, const float* __restrict__ bv,
                         const float* __restrict__ plifw, const float* __restrict__ outw,
                         float* __restrict__ out, int t) {
    int blk = blockIdx.x;
    int b = blk >> 7, co = blk & 127;
    int tid = threadIdx.x;

    float wsig[6];
#pragma unroll
    for (int i = 0; i < 6; i++) wsig[i] = sigmoidf(__ldg(outw + i));

    float sigp[5], ga[5], mm[5], bbias[5], cv[5];
#pragma unroll
    for (int i = 0; i < 5; i++) {
        sigp[i] = sigmoidf(__ldg(plifw + 1 + i));
        float inv = 1.0f / sqrtf(__ldg(bv + i * 128 + co) + 1e-5f);
        ga[i]    = __ldg(bg + i * 128 + co) * inv;
        mm[i]    = __ldg(bm + i * 128 + co);
        bbias[i] = __ldg(bb + i * 128 + co);
        cv[i]    = g_c[b * NN + 1 + i];
    }

    float lsum[5] = {0, 0, 0, 0, 0};
    const int base0 = (b * COUT + co) * NPIX;
#pragma unroll
    for (int q = 0; q < 4; q++) {
        int pp = tid + q * 256;
        float o0 = g_out0[base0 + pp];
        float accO = wsig[0] * o0;
#pragma unroll
        for (int i = 0; i < 5; i++) {
            float yv = g_Y[((long long)b * COG + i * 128 + co) * NPIX + pp];
            float pre = cv[i] * yv;
            float civ = (pre - mm[i]) * ga[i] + bbias[i];
            int vidx = ((i * BB + b) * COUT + co) * NPIX + pp;
            float vp = g_vn[vidx];
            float v = vp + (civ - vp) * sigp[i];
            float sp = (v >= 1.0f) ? 1.0f : 0.0f;
            g_vn[vidx] = v * (1.0f - sp);
            accO += wsig[i + 1] * sp;
            lsum[i] += sp;
        }
        out[((long long)(t * BB + b) * COUT + co) * NPIX + pp] = accO;
    }

    __shared__ float red[256];
    for (int i = 0; i < 5; i++) {
        red[tid] = lsum[i];
        __syncthreads();
        for (int st = 128; st > 0; st >>= 1) {
            if (tid < st) red[tid] += red[tid + st];
            __syncthreads();
        }
        if (tid == 0) g_nodesum[i * (BB * COUT) + b * COUT + co] = red[0];
        __syncthreads();
    }
}

// ---------------- K6: all-node feats + final traces update ----------------
__global__ void k6_feats(const float* __restrict__ ftw, const float* __restrict__ ftb) {
    int b = blockIdx.x / NN, n = blockIdx.x % NN;
    int co = threadIdx.x;
    __shared__ float mv[128];
    mv[co] = (n == 0) ? g_m0[b * 128 + co]
                      : g_nodesum[(n - 1) * (BB * COUT) + b * 128 + co] * (1.0f / 1024.0f);
    __syncthreads();
    float acc = 0.0f;
    for (int ci = 0; ci < 128; ci++) acc += mv[ci] * __ldg(ftw + co * 128 + ci);
    float f = fmaxf(acc + __ldg(ftb + co), 0.0f);
    int ti = (b * NN + n) * 128 + co;
    g_traces[ti] = 0.6f * g_traces[ti] + 0.4f * f;
}

// ---------------- launcher ----------------
extern "C" void kernel_launch(void* const* d_in, const int* in_sizes, int n_in,
                              void* d_out, int out_size) {
    const float* x       = (const float*)d_in[0];
    const float* conv0_w = (const float*)d_in[1];
    const float* bn0_g   = (const float*)d_in[2];
    const float* bn0_b   = (const float*)d_in[3];
    const float* bn0_m   = (const float*)d_in[4];
    const float* bn0_v   = (const float*)d_in[5];
    const float* convs_w = (const float*)d_in[6];
    const float* bns_g   = (const float*)d_in[7];
    const float* bns_b   = (const float*)d_in[8];
    const float* bns_m   = (const float*)d_in[9];
    const float* bns_v   = (const float*)d_in[10];
    const float* plif_w  = (const float*)d_in[11];
    const float* ft_w    = (const float*)d_in[12];
    const float* ft_b    = (const float*)d_in[13];
    const float* gat_W   = (const float*)d_in[14];
    const float* gat_a   = (const float*)d_in[15];
    const float* out_w   = (const float*)d_in[16];
    float* out = (float*)d_out;

    cudaFuncSetAttribute(k4_mma, cudaFuncAttributeMaxDynamicSharedMemorySize, K4_SMEM);

    kzero<<<4096, 256>>>();
    ka_build<<<(COG * KTOT + 255) / 256, 256>>>(convs_w);

    for (int t = 0; t < TT; t++) {
        k1_conv0<<<(BB * COUT * NPIX) / 256, 256>>>(
            x + (long long)t * BB * CINC * HIMG * WIMG,
            conv0_w, bn0_g, bn0_b, bn0_m, bn0_v, plif_w);
        k2a_mean<<<BB * COUT, 256>>>();
        k2b_feat0<<<BB, 128>>>(ft_w, ft_b);
        k3_gat<<<BB, 192>>>(gat_W, gat_a);
        kb_im2col<<<dim3(32, BB), 256>>>();
        k4_mma<<<dim3(5, 4, BB), 256, K4_SMEM>>>();
        k5_nodes<<<BB * COUT, 256>>>(bns_g, bns_b, bns_m, bns_v, plif_w, out_w, out, t);
        k6_feats<<<BB * NN, 128>>>(ft_w, ft_b);
    }
}

// round 14
// speedup vs baseline: 2.1311x; 1.2303x over previous
#include <cuda_runtime.h>
#include <cuda_bf16.h>
#include <cuda_fp16.h>
#include <math.h>
#include <stdint.h>

// ---------------- problem constants ----------------
#define TT    4
#define BB    16
#define CINC  3
#define HIMG  64
#define WIMG  64
#define NN    6
#define COUT  128
#define HP    32
#define WP    32
#define NPIX  1024
#define NODE5 5
#define KTOT  1152          // 128 ci * 9 taps
#define COG   640           // 5 nodes * 128 out channels
#define NCHUNK 18           // 1152 / 64

// ---------------- persistent device state ----------------
__device__ float g_v0[BB*COUT*HIMG*WIMG];
__device__ float g_vn[NODE5*BB*COUT*NPIX];
__device__ float g_traces[BB*NN*COUT];
__device__ float g_out0[BB*COUT*NPIX];
__device__ float g_m0[BB*COUT];
__device__ float g_Y[BB*COG*NPIX];
__device__ float g_c[BB*NN];
__device__ float g_nodesum[NODE5*BB*COUT];
__device__ __half g_A2[2*COG*KTOT];              // 2-split fp16 weights, k = tap*128+ci
__device__ __half g_out0T[BB*NPIX*COUT];         // out0 transposed [b][p][ci], fp16 exact

__device__ __forceinline__ float sigmoidf(float x) { return 1.0f / (1.0f + expf(-x)); }

// ================= baseline-ISA helpers (sm_80+: valid on sm_103 target) =======
__device__ __forceinline__ uint32_t smem_u32(const void* p) {
    uint32_t a;
    asm("{ .reg .u64 t; cvta.to.shared.u64 t, %1; cvt.u32.u64 %0, t; }" : "=r"(a) : "l"(p));
    return a;
}
#define SWZ128(off) ((off) ^ (((off) >> 3) & 0x70))
#define CP16(dst, src) \
    asm volatile("cp.async.cg.shared.global [%0], [%1], 16;" :: "r"(dst), "l"(src) : "memory")
#define CP16Z(dst, src, srcsz) \
    asm volatile("cp.async.cg.shared.global [%0], [%1], 16, %2;" \
                 :: "r"(dst), "l"(src), "r"(srcsz) : "memory")
#define CP_COMMIT() asm volatile("cp.async.commit_group;" ::: "memory")
#define CP_WAIT(n)  asm volatile("cp.async.wait_group %0;" :: "n"(n) : "memory")

__device__ __forceinline__ void ldsm4(uint32_t& r0, uint32_t& r1, uint32_t& r2,
                                      uint32_t& r3, uint32_t addr) {
    asm volatile("ldmatrix.sync.aligned.m8n8.x4.shared.b16 {%0,%1,%2,%3}, [%4];"
                 : "=r"(r0), "=r"(r1), "=r"(r2), "=r"(r3) : "r"(addr));
}
__device__ __forceinline__ void mma_f16(float* c, uint32_t a0, uint32_t a1,
                                        uint32_t a2, uint32_t a3,
                                        uint32_t b0, uint32_t b1) {
    asm volatile("mma.sync.aligned.m16n8k16.row.col.f32.f16.f16.f32 "
                 "{%0,%1,%2,%3}, {%4,%5,%6,%7}, {%8,%9}, {%0,%1,%2,%3};"
                 : "+f"(c[0]), "+f"(c[1]), "+f"(c[2]), "+f"(c[3])
                 : "r"(a0), "r"(a1), "r"(a2), "r"(a3), "r"(b0), "r"(b1));
}

// ---------------- K0: zero persistent state ----------------
__global__ void kzero() {
    long long tid = (long long)blockIdx.x * blockDim.x + threadIdx.x;
    long long stride = (long long)gridDim.x * blockDim.x;
    for (long long i = tid; i < (long long)BB*COUT*HIMG*WIMG; i += stride) g_v0[i] = 0.0f;
    for (long long i = tid; i < (long long)NODE5*BB*COUT*NPIX; i += stride) g_vn[i] = 0.0f;
    for (long long i = tid; i < (long long)BB*NN*COUT; i += stride) g_traces[i] = 0.0f;
}

// ---------------- Ka: build 2-way fp16 split of node-conv weights (once) --------
__global__ void ka_build(const float* __restrict__ w) {
    int idx = blockIdx.x * 256 + threadIdx.x;
    if (idx >= COG * KTOT) return;
    int cog = idx / KTOT;
    int k   = idx - cog * KTOT;
    int tap = k >> 7;
    int ci  = k & 127;
    float v = w[cog * KTOT + ci * 9 + tap];
    __half h0 = __float2half_rn(v);
    float f0 = __half2float(h0);
    __half h1 = __float2half_rn(v - f0);
    g_A2[idx]             = h0;
    g_A2[COG*KTOT + idx]  = h1;
}

// ---------------- K1: conv0(3->128)+BN+PLIF0+2x2 avgpool -> out0 ----------------
__global__ void k1_conv0(const float* __restrict__ xt, const float* __restrict__ w0,
                         const float* __restrict__ bg, const float* __restrict__ bb,
                         const float* __restrict__ bm, const float* __restrict__ bv,
                         const float* __restrict__ plifw) {
    int tid = blockIdx.x * 256 + threadIdx.x;
    int p   = tid & (NPIX - 1);
    int co  = (tid >> 10) & 127;
    int b   = tid >> 17;
    int hp  = p >> 5, wp = p & 31;

    float w[27];
#pragma unroll
    for (int j = 0; j < 27; j++) w[j] = __ldg(w0 + co * 27 + j);
    float inv   = 1.0f / sqrtf(__ldg(bv + co) + 1e-5f);
    float ga    = __ldg(bg + co) * inv;
    float mm    = __ldg(bm + co);
    float bbias = __ldg(bb + co);
    float sig   = sigmoidf(__ldg(plifw));

    const float* xb = xt + b * (CINC * HIMG * WIMG);
    float s4 = 0.0f;
#pragma unroll
    for (int dy = 0; dy < 2; dy++)
#pragma unroll
        for (int dx = 0; dx < 2; dx++) {
            int y0 = 2 * hp + dy, x0 = 2 * wp + dx;
            float acc = 0.0f;
#pragma unroll
            for (int ci = 0; ci < 3; ci++)
#pragma unroll
                for (int ky = 0; ky < 3; ky++) {
                    int yy = y0 + ky - 1;
                    if (yy < 0 || yy >= HIMG) continue;
#pragma unroll
                    for (int kx = 0; kx < 3; kx++) {
                        int xx = x0 + kx - 1;
                        if (xx < 0 || xx >= WIMG) continue;
                        acc += xb[ci * (HIMG*WIMG) + yy * WIMG + xx] * w[ci * 9 + ky * 3 + kx];
                    }
                }
            float xc = (acc - mm) * ga + bbias;
            int vi = ((b * COUT + co) * HIMG + y0) * WIMG + x0;
            float vprev = g_v0[vi];
            float v = vprev + (xc - vprev) * sig;
            float sp = (v >= 1.0f) ? 1.0f : 0.0f;
            g_v0[vi] = v * (1.0f - sp);
            s4 += sp;
        }
    g_out0[(b * COUT + co) * NPIX + p] = s4 * 0.25f;
}

// ---------------- KbT: transpose out0 -> out0T[b][p][ci] fp16 -------------------
// grid (4 ptiles x 4 citiles, 16 b), 256 threads, smem 32x257 f32
__global__ void kbT_transpose() {
    int tile = blockIdx.x;
    int pt = tile >> 2, ct = tile & 3;
    int b  = blockIdx.y;
    int p0 = pt * 256, ci0 = ct * 32;
    __shared__ float st[32][257];
    int tid = threadIdx.x;
#pragma unroll 8
    for (int r = 0; r < 32; r++)
        st[r][tid] = g_out0[(b * 128 + ci0 + r) * NPIX + p0 + tid];
    __syncthreads();
    __half h[32];
#pragma unroll
    for (int ci = 0; ci < 32; ci++) h[ci] = __float2half_rn(st[ci][tid]);
    uint4* dst = reinterpret_cast<uint4*>(g_out0T + (long long)(b * NPIX + p0 + tid) * COUT + ci0);
    const uint4* src = reinterpret_cast<const uint4*>(h);
#pragma unroll
    for (int q = 0; q < 4; q++) dst[q] = src[q];
}

// ---------------- K2: fused spatial mean + feat0 + traces[:,0,:] ----------------
// grid 16 (b), 256 threads
__global__ void k2_fused(const float* __restrict__ ftw, const float* __restrict__ ftb) {
    int b = blockIdx.x;
    int tid = threadIdx.x, w = tid >> 5, lane = tid & 31;
    __shared__ float mv[128];
#pragma unroll 1
    for (int j = 0; j < 16; j++) {
        int co = w * 16 + j;
        const float* src = g_out0 + (b * 128 + co) * NPIX;
        float s = 0.0f;
#pragma unroll
        for (int i = 0; i < 32; i++) s += src[i * 32 + lane];
#pragma unroll
        for (int o = 16; o > 0; o >>= 1) s += __shfl_xor_sync(0xFFFFFFFFu, s, o);
        if (lane == 0) {
            float m = s * (1.0f / 1024.0f);
            mv[co] = m;
            g_m0[b * 128 + co] = m;
        }
    }
    __syncthreads();
    if (tid < 128) {
        float acc = 0.0f;
        for (int ci = 0; ci < 128; ci++) acc += mv[ci] * __ldg(ftw + tid * 128 + ci);
        float f = fmaxf(acc + __ldg(ftb + tid), 0.0f);
        int ti = (b * NN + 0) * 128 + tid;
        g_traces[ti] = 0.6f * g_traces[ti] + 0.4f * f;
    }
}

// ---------------- K3: GAT adjacency + softmax + top-k prune + diffusion -> c ----
__global__ void k3_gat(const float* __restrict__ gw, const float* __restrict__ ga) {
    int b = blockIdx.x;
    __shared__ float tr[768], hps[768], e1s[24], e2s[24];
    int tid = threadIdx.x;
    for (int o = tid; o < 768; o += 192) tr[o] = g_traces[b * 768 + o];
    __syncthreads();
    for (int o = tid; o < 768; o += 192) {
        int n = o >> 7, co = o & 127;
        float s = 0.0f;
        for (int ci = 0; ci < 128; ci++) s += tr[n * 128 + ci] * __ldg(gw + co * 128 + ci);
        hps[o] = s;
    }
    __syncthreads();
    if (tid < 24) {
        int n = tid >> 2, h = tid & 3;
        float s1 = 0.0f, s2 = 0.0f;
        for (int d = 0; d < 32; d++) {
            float hv = hps[n * 128 + h * 32 + d];
            s1 += hv * __ldg(ga + h * 64 + d);
            s2 += hv * __ldg(ga + h * 64 + 32 + d);
        }
        e1s[tid] = s1; e2s[tid] = s2;
    }
    __syncthreads();
    if (tid == 0) {
        float S[6][6], Sp[6][6], adj[6][6], op[6][6], deg[6], dis[6];
        for (int i = 0; i < 6; i++)
            for (int j = 0; j < 6; j++) {
                float s = 0.0f;
                for (int h = 0; h < 4; h++) {
                    float eij = e1s[i*4+h] + e2s[j*4+h];
                    eij = eij > 0.0f ? eij : 0.2f * eij;
                    float eji = e1s[j*4+h] + e2s[i*4+h];
                    eji = eji > 0.0f ? eji : 0.2f * eji;
                    s += 0.5f * (eij + eji);
                }
                S[i][j] = s * 0.25f;
            }
        for (int i = 0; i < 6; i++) {
            float y[6], mx = -1e30f;
            for (int j = 0; j < 6; j++) { y[j] = S[i][j] / 0.01f; mx = fmaxf(mx, y[j]); }
            float den = 0.0f;
            for (int j = 0; j < 6; j++) { y[j] = expf(y[j] - mx); den += y[j]; }
            for (int j = 0; j < 6; j++) S[i][j] = y[j] / den;
        }
        for (int i = 0; i < 6; i++) {
            float v[6];
            for (int j = 0; j < 6; j++) v[j] = S[i][j];
            for (int a = 0; a < 3; a++) {
                int mi = a;
                for (int q = a + 1; q < 6; q++) if (v[q] > v[mi]) mi = q;
                float tmp = v[a]; v[a] = v[mi]; v[mi] = tmp;
            }
            float kth = v[2];
            for (int j = 0; j < 6; j++)
                Sp[i][j] = S[i][j] * ((S[i][j] >= kth) ? 1.0f : 0.0f);
        }
        for (int i = 0; i < 6; i++) {
            float dsum = 0.0f;
            for (int j = 0; j < 6; j++) { adj[i][j] = 0.5f * (Sp[i][j] + Sp[j][i]); dsum += adj[i][j]; }
            deg[i] = dsum;
        }
        for (int i = 0; i < 6; i++) dis[i] = 1.0f / sqrtf(deg[i] + 1e-6f);
        for (int i = 0; i < 6; i++)
            for (int j = 0; j < 6; j++) op[i][j] = dis[i] * adj[i][j] * dis[j];
        for (int i = 0; i < 6; i++) {
            float cv = 0.0f;
            for (int j = 0; j < 6; j++) cv += op[i][j] * op[j][0];
            g_c[b * NN + i] = cv;
        }
    }
}

// ---------------- K4: fp16 mma.sync GEMM, on-the-fly im2col, 3-stage pipe -------
// grid (5 co-tiles, 4 pix-tiles, 16 b), 256 threads (8 warps: 2m x 4n).
// D[128 x 256] = sum_{split,k} A2[split][co][k] * B[pix][k], B built from out0T.
#define ASTAGE 32768                 // 2 splits * 128 rows * 128B
#define BSTAGE 32768                 // 256 rows * 128B
#define STAGE  (ASTAGE + BSTAGE)     // 65536
#define K4_SMEM (3 * STAGE)          // 196608

__device__ __forceinline__ void load_chunk(uint32_t sb, int stage, int c,
                                           const __half* gA, const __half* gBT,
                                           int p0, int tid) {
    uint32_t abase = sb + stage * STAGE;
    uint32_t bbase = abase + ASTAGE;
    const int tap = c >> 1;
    const int ky  = tap / 3;            // 0..2 (minus 1 applied below)
    const int kx  = tap - ky * 3;
    const int ci0 = (c & 1) * 64;
    // A: 2 splits * 128 rows * 8 x 16B = 2048 cp16
#pragma unroll
    for (int i = 0; i < 8; i++) {
        int idx = i * 256 + tid;
        int split = idx >> 10;
        int rem = idx & 1023;
        int r = rem >> 3, j = rem & 7;
        const __half* src = gA + (long long)(split * COG + r) * KTOT + c * 64 + j * 8;
        uint32_t off = (uint32_t)(r * 128 + j * 16);
        CP16(abase + split * 16384 + SWZ128(off), src);
    }
    // B: 256 rows * 8 x 16B = 2048 cp16, tap-shifted gather with zero-fill
#pragma unroll
    for (int i = 0; i < 8; i++) {
        int idx = i * 256 + tid;
        int n = idx >> 3, j = idx & 7;
        int p = p0 + n;
        int y = (p >> 5) + ky - 1;
        int x = (p & 31) + kx - 1;
        uint32_t valid = ((unsigned)y < 32u) && ((unsigned)x < 32u);
        int pp = valid ? (y * 32 + x) : 0;
        const __half* src = gBT + (long long)pp * COUT + ci0 + j * 8;
        uint32_t off = (uint32_t)(n * 128 + j * 16);
        CP16Z(bbase + SWZ128(off), src, valid ? 16u : 0u);
    }
}

__global__ __launch_bounds__(256, 1) void k4_mma() {
    extern __shared__ char smem[];
    uint32_t sb = smem_u32(smem);
    const int tid = threadIdx.x;
    const int wid = tid >> 5;
    const int lid = tid & 31;
    const int co0 = blockIdx.x * 128;
    const int p0  = blockIdx.y * 256;
    const int b   = blockIdx.z;
    const int wm  = (wid >> 2) * 64;   // warp m offset (0 / 64)
    const int wn  = (wid & 3) * 64;    // warp n offset (0..192)

    const __half* gA  = g_A2 + (long long)co0 * KTOT;
    const __half* gBT = g_out0T + (long long)b * NPIX * COUT;

    float acc[4][8][4];
#pragma unroll
    for (int i = 0; i < 4; i++)
#pragma unroll
        for (int j = 0; j < 8; j++)
#pragma unroll
            for (int q = 0; q < 4; q++) acc[i][j][q] = 0.0f;

    const int lrow = lid & 15;
    const int lcol = (lid >> 4) * 16;

    load_chunk(sb, 0, 0, gA, gBT, p0, tid);
    CP_COMMIT();
    load_chunk(sb, 1, 1, gA, gBT, p0, tid);
    CP_COMMIT();

#pragma unroll 1
    for (int c = 0; c < NCHUNK; c++) {
        const int s = c % 3;
        if (c + 2 < NCHUNK) {
            load_chunk(sb, (c + 2) % 3, c + 2, gA, gBT, p0, tid);
            CP_COMMIT();
            CP_WAIT(2);
        } else if (c + 1 < NCHUNK) {
            CP_WAIT(1);
        } else {
            CP_WAIT(0);
        }
        __syncthreads();

        const uint32_t abase = sb + s * STAGE;
        const uint32_t bbase = abase + ASTAGE;
#pragma unroll
        for (int ks = 0; ks < 4; ks++) {
            const int kb = ks * 32;
            uint32_t bf[4][4];
#pragma unroll
            for (int q = 0; q < 4; q++) {
                uint32_t addr = bbase + SWZ128((uint32_t)((wn + q * 16 + lrow) * 128 + kb + lcol));
                ldsm4(bf[q][0], bf[q][1], bf[q][2], bf[q][3], addr);
            }
#pragma unroll
            for (int split = 0; split < 2; split++) {
                const uint32_t asb = abase + split * 16384;
#pragma unroll
                for (int mt = 0; mt < 4; mt++) {
                    uint32_t a0, a1, a2, a3;
                    uint32_t addr = asb + SWZ128((uint32_t)((wm + mt * 16 + lrow) * 128 + kb + lcol));
                    ldsm4(a0, a1, a2, a3, addr);
#pragma unroll
                    for (int q = 0; q < 4; q++) {
                        mma_f16(acc[mt][2*q],   a0, a1, a2, a3, bf[q][0], bf[q][2]);
                        mma_f16(acc[mt][2*q+1], a0, a1, a2, a3, bf[q][1], bf[q][3]);
                    }
                }
            }
        }
        __syncthreads();
    }

    // epilogue: accum regs -> g_Y (32B-sector-aligned float2 stores)
    const int er = lid >> 2;
    const int ec = (lid & 3) * 2;
    float* ybase = g_Y + (long long)(b * COG + co0 + wm) * NPIX + p0 + wn;
#pragma unroll
    for (int mt = 0; mt < 4; mt++) {
#pragma unroll
        for (int nt = 0; nt < 8; nt++) {
            float* y0 = ybase + (long long)(mt * 16 + er) * NPIX + nt * 8 + ec;
            *reinterpret_cast<float2*>(y0) = make_float2(acc[mt][nt][0], acc[mt][nt][1]);
            float* y1 = y0 + 8 * NPIX;
            *reinterpret_cast<float2*>(y1) = make_float2(acc[mt][nt][2], acc[mt][nt][3]);
        }
    }
}

// ---------------- K5: node BN + PLIF + weighted output + spike sums ----------
__global__ void k5_nodes(const float* __restrict__ bg, const float* __restrict__ bb,
                         const float* __restrict__ bm, const float* __restrict__ bv,
                         const float* __restrict__ plifw, const float* __restrict__ outw,
                         float* __restrict__ out, int t) {
    int blk = blockIdx.x;
    int b = blk >> 7, co = blk & 127;
    int tid = threadIdx.x;

    float wsig[6];
#pragma unroll
    for (int i = 0; i < 6; i++) wsig[i] = sigmoidf(__ldg(outw + i));

    float sigp[5], ga[5], mm[5], bbias[5], cv[5];
#pragma unroll
    for (int i = 0; i < 5; i++) {
        sigp[i] = sigmoidf(__ldg(plifw + 1 + i));
        float inv = 1.0f / sqrtf(__ldg(bv + i * 128 + co) + 1e-5f);
        ga[i]    = __ldg(bg + i * 128 + co) * inv;
        mm[i]    = __ldg(bm + i * 128 + co);
        bbias[i] = __ldg(bb + i * 128 + co);
        cv[i]    = g_c[b * NN + 1 + i];
    }

    float lsum[5] = {0, 0, 0, 0, 0};
    const int base0 = (b * COUT + co) * NPIX;
#pragma unroll
    for (int q = 0; q < 4; q++) {
        int pp = tid + q * 256;
        float o0 = g_out0[base0 + pp];
        float accO = wsig[0] * o0;
#pragma unroll
        for (int i = 0; i < 5; i++) {
            float yv = g_Y[((long long)b * COG + i * 128 + co) * NPIX + pp];
            float pre = cv[i] * yv;
            float civ = (pre - mm[i]) * ga[i] + bbias[i];
            int vidx = ((i * BB + b) * COUT + co) * NPIX + pp;
            float vp = g_vn[vidx];
            float v = vp + (civ - vp) * sigp[i];
            float sp = (v >= 1.0f) ? 1.0f : 0.0f;
            g_vn[vidx] = v * (1.0f - sp);
            accO += wsig[i + 1] * sp;
            lsum[i] += sp;
        }
        out[((long long)(t * BB + b) * COUT + co) * NPIX + pp] = accO;
    }

    __shared__ float red[256];
    for (int i = 0; i < 5; i++) {
        red[tid] = lsum[i];
        __syncthreads();
        for (int st = 128; st > 0; st >>= 1) {
            if (tid < st) red[tid] += red[tid + st];
            __syncthreads();
        }
        if (tid == 0) g_nodesum[i * (BB * COUT) + b * COUT + co] = red[0];
        __syncthreads();
    }
}

// ---------------- K6: all-node feats + final traces update ----------------
__global__ void k6_feats(const float* __restrict__ ftw, const float* __restrict__ ftb) {
    int b = blockIdx.x / NN, n = blockIdx.x % NN;
    int co = threadIdx.x;
    __shared__ float mv[128];
    mv[co] = (n == 0) ? g_m0[b * 128 + co]
                      : g_nodesum[(n - 1) * (BB * COUT) + b * 128 + co] * (1.0f / 1024.0f);
    __syncthreads();
    float acc = 0.0f;
    for (int ci = 0; ci < 128; ci++) acc += mv[ci] * __ldg(ftw + co * 128 + ci);
    float f = fmaxf(acc + __ldg(ftb + co), 0.0f);
    int ti = (b * NN + n) * 128 + co;
    g_traces[ti] = 0.6f * g_traces[ti] + 0.4f * f;
}

// ---------------- launcher ----------------
extern "C" void kernel_launch(void* const* d_in, const int* in_sizes, int n_in,
                              void* d_out, int out_size) {
    const float* x       = (const float*)d_in[0];
    const float* conv0_w = (const float*)d_in[1];
    const float* bn0_g   = (const float*)d_in[2];
    const float* bn0_b   = (const float*)d_in[3];
    const float* bn0_m   = (const float*)d_in[4];
    const float* bn0_v   = (const float*)d_in[5];
    const float* convs_w = (const float*)d_in[6];
    const float* bns_g   = (const float*)d_in[7];
    const float* bns_b   = (const float*)d_in[8];
    const float* bns_m   = (const float*)d_in[9];
    const float* bns_v   = (const float*)d_in[10];
    const float* plif_w  = (const float*)d_in[11];
    const float* ft_w    = (const float*)d_in[12];
    const float* ft_b    = (const float*)d_in[13];
    const float* gat_W   = (const float*)d_in[14];
    const float* gat_a   = (const float*)d_in[15];
    const float* out_w   = (const float*)d_in[16];
    float* out = (float*)d_out;

    cudaFuncSetAttribute(k4_mma, cudaFuncAttributeMaxDynamicSharedMemorySize, K4_SMEM);

    kzero<<<4096, 256>>>();
    ka_build<<<(COG * KTOT + 255) / 256, 256>>>(convs_w);

    for (int t = 0; t < TT; t++) {
        k1_conv0<<<(BB * COUT * NPIX) / 256, 256>>>(
            x + (long long)t * BB * CINC * HIMG * WIMG,
            conv0_w, bn0_g, bn0_b, bn0_m, bn0_v, plif_w);
        kbT_transpose<<<dim3(16, BB), 256>>>();
        k2_fused<<<BB, 256>>>(ft_w, ft_b);
        k3_gat<<<BB, 192>>>(gat_W, gat_a);
        k4_mma<<<dim3(5, 4, BB), 256, K4_SMEM>>>();
        k5_nodes<<<BB * COUT, 256>>>(bns_g, bns_b, bns_m, bns_v, plif_w, out_w, out, t);
        k6_feats<<<BB * NN, 128>>>(ft_w, ft_b);
    }
}